// round 10
// baseline (speedup 1.0000x reference)
#include <cuda_runtime.h>
#include <math.h>

#define MAXN 100000
#define MAXE 800000

// Scratch (no allocation allowed in kernel_launch).
// Invariant: g_deg and g_sum are all-zero at kernel_launch entry.
//  - first call: __device__ globals are zero-initialized at module load
//  - later calls: k_nodedeg re-zeros g_sum, k_div re-zeros g_deg
__device__ float g_deg[MAXN];        // sum |val| per destination
__device__ float g_sum[MAXN];        // softmax denominator per destination
__device__ float g_feat[MAXN * 32];  // per-node [f@W1_top | f@W1_bot]

typedef unsigned long long u64;

__device__ __forceinline__ float leaky(float v) {
    return fmaxf(v, 0.1f * v);       // branchless: FMUL + FMNMX
}

// packed fp32x2 ops: per-32-bit-lane fp32 arithmetic in b64 registers
__device__ __forceinline__ void fma2(u64& c, u64 a, u64 b) {
    asm("fma.rn.f32x2 %0, %1, %2, %0;" : "+l"(c) : "l"(a), "l"(b));
}
__device__ __forceinline__ u64 add2(u64 a, u64 b) {
    u64 r;
    asm("add.rn.f32x2 %0, %1, %2;" : "=l"(r) : "l"(a), "l"(b));
    return r;
}
__device__ __forceinline__ u64 pack2(float lo, float hi) {
    u64 r;
    asm("mov.b64 %0, {%1, %2};" : "=l"(r) : "f"(lo), "f"(hi));
    return r;
}
__device__ __forceinline__ float2 unpack2(u64 v) {
    float lo, hi;
    asm("mov.b64 {%0, %1}, %2;" : "=f"(lo), "=f"(hi) : "l"(v));
    return make_float2(lo, hi);
}

// ---------------------------------------------------------------------------
// Kernel 1 (fused, 3 block ranges):
//   [0, nodeBlocks)          : projection g[n] = f[n] @ Wcat (128 nodes/block)
//   [nodeBlocks, +degBlocks) : deg[i] += |val[e]|
//   [.., +N blocks)          : g_sum[n] = 0 (restores invariant for k_edge)
//
// Projection (register-tiled, no f staging):
//   warp = 32 nodes x 16 cols; lane grid 8(lrow) x 4(lcol); lane tile =
//   4 nodes x 4 cols. f read directly from global via LDG.128 (L1-resident:
//   consecutive k-chunks reuse each 128B line). W in smem, fetched as one
//   ulonglong2 per lane per k — arrives pre-packed as col-pair b64 operands.
// ---------------------------------------------------------------------------
__global__ void __launch_bounds__(256, 4) k_nodedeg(
        const float* __restrict__ f, const float* __restrict__ W1,
        const int* __restrict__ ind, const float* __restrict__ val,
        int N, int E, int nodeBlocks, int degBlocks) {
    __shared__ float sW[128 * 32];   // 16 KB: Wcat[k][c] row-major

    if (blockIdx.x >= nodeBlocks) {
        int b = blockIdx.x - nodeBlocks;
        if (b < degBlocks) {
            int e = b * blockDim.x + threadIdx.x;
            if (e < E) atomicAdd(&g_deg[ind[e]], fabsf(val[e]));
        } else {
            int n = (b - degBlocks) * blockDim.x + threadIdx.x;
            if (n < N) g_sum[n] = 0.f;
        }
        return;
    }

    // Wcat[k][c] = (c<16) ? W1[k][c] : W1[128+k][c-16], row-major 32 per k
    for (int t = threadIdx.x; t < 128 * 32; t += blockDim.x) {
        int k = t >> 5;
        int c = t & 31;
        sW[t] = (c < 16) ? W1[k * 16 + c] : W1[(128 + k) * 16 + (c - 16)];
    }
    __syncthreads();

    int warp = threadIdx.x >> 5;
    int lane = threadIdx.x & 31;
    int lrow = lane >> 2;            // 0..7
    int lcol = lane & 3;             // 0..3
    int ng = warp >> 1;              // node group 0..3
    int cg = warp & 1;               // col group 0..1

    int nbase = blockIdx.x * 128 + ng * 32 + lrow * 4;
    // per-node row offsets in float4 units (clamped for tail block)
    int off[4];
#pragma unroll
    for (int n = 0; n < 4; n++) off[n] = min(nbase + n, N - 1) * 32;

    const float4* f4 = (const float4*)f;
    const ulonglong2* sWu = (const ulonglong2*)sW;  // 8 u2 per k-row
    int woff = cg * 4 + lcol;                       // u2 col index within row

    u64 acc[4][2];
#pragma unroll
    for (int n = 0; n < 4; n++) { acc[n][0] = 0ull; acc[n][1] = 0ull; }

#pragma unroll 4
    for (int ki = 0; ki < 32; ki++) {               // 4 k per iteration
        float4 fr[4];
#pragma unroll
        for (int n = 0; n < 4; n++) fr[n] = f4[off[n] + ki];
#pragma unroll
        for (int j = 0; j < 4; j++) {
            ulonglong2 wk = sWu[(ki * 4 + j) * 8 + woff];  // 1 wf, pre-packed
#pragma unroll
            for (int n = 0; n < 4; n++) {
                float fv = (j == 0) ? fr[n].x : (j == 1) ? fr[n].y
                         : (j == 2) ? fr[n].z : fr[n].w;
                u64 a = pack2(fv, fv);
                fma2(acc[n][0], a, wk.x);
                fma2(acc[n][1], a, wk.y);
            }
        }
    }

    // epilogue: 4 cols contiguous -> direct STG.128, coalesced across lcol
#pragma unroll
    for (int n = 0; n < 4; n++) {
        int node = nbase + n;
        if (node < N) {
            float2 a = unpack2(acc[n][0]);
            float2 b = unpack2(acc[n][1]);
            ((float4*)(g_feat + (size_t)node * 32 + cg * 16 + lcol * 4))[0] =
                make_float4(a.x, a.y, b.x, b.y);
        }
    }
}

// ---------------------------------------------------------------------------
// Kernel 2 (fused edge MLP + exp + sum):
//   Phase A: stage edge indices to smem.
//   Phase B: cooperative gather — 8 lanes per edge fetch gi-top/gj-bot float4s.
//   Phase C: thread-per-edge MLP, column-at-a-time vs transposed W2
//            (stride 20 -> weights as 4 broadcast LDS.128, pre-packed pairs),
//            packed f32x2 FMAs/adds. ex=__expf(logit) (softmax shift-
//            invariant, logits O(+-6): no max pass), out[e]=ex, atomic sum[i].
// ---------------------------------------------------------------------------
__global__ void __launch_bounds__(256, 5) k_edge(
        const int* __restrict__ ind, const float* __restrict__ val,
        const float* __restrict__ b1, const float* __restrict__ W2,
        const float* __restrict__ b2, const float* __restrict__ Wc,
        const float* __restrict__ bc, float* __restrict__ out, int E) {
    __shared__ float sX[256 * 34];     // staged [gi_top(16) | gj_bot(16)] per edge
    __shared__ int   sI[256], sJ[256];
    __shared__ float sW2T[17 * 20];    // transposed, stride 20 (16B aligned rows)
    __shared__ float sB1[16], sB2[17], sWc[17];
    __shared__ float sBc;

    int tid = threadIdx.x;
    for (int t = tid; t < 289; t += blockDim.x) {
        int r = t / 17, c = t % 17;
        sW2T[c * 20 + r] = W2[t];
    }
    if (tid < 16) sB1[tid] = b1[tid];
    if (tid >= 32 && tid < 49) sB2[tid - 32] = b2[tid - 32];
    if (tid >= 64 && tid < 81) sWc[tid - 64] = Wc[tid - 64];
    if (tid == 96) sBc = bc[0];

    // Phase A
    int e0 = blockIdx.x * 256;
    int e = e0 + tid;
    bool valid = (e < E);
    sI[tid] = valid ? ind[e] : 0;
    sJ[tid] = valid ? ind[E + e] : 0;
    __syncthreads();

    // Phase B: 2048 float4 gather tasks, 8 per edge
#pragma unroll
    for (int it = 0; it < 8; it++) {
        int t = tid + it * 256;
        int eL = t >> 3;
        int p = t & 7;                              // 0-3: gi row, 4-7: gj row
        int node = (p < 4) ? sI[eL] : sJ[eL];
        float4 v = ((const float4*)(g_feat + (size_t)node * 32))[p];
        float* dst = &sX[eL * 34 + p * 4];          // even offset -> 8B aligned
        ((float2*)dst)[0] = make_float2(v.x, v.y);
        ((float2*)dst)[1] = make_float2(v.z, v.w);
    }
    __syncthreads();

    if (!valid) return;

    int i = sI[tid];
    const u64* sxu = (const u64*)(sX + tid * 34);
    const u64* b1u = (const u64*)sB1;

    // x = leaky(gi_top + gj_bot + b1) via packed adds, packed into 8 b64 pairs
    u64 xp[8];
#pragma unroll
    for (int q = 0; q < 8; q++) {
        u64 s = add2(add2(sxu[q], sxu[8 + q]), b1u[q]);
        float2 v = unpack2(s);
        xp[q] = pack2(leaky(v.x), leaky(v.y));
    }
    float x16 = __fdividef(fabsf(val[e]), g_deg[i]);

    // column-at-a-time second layer + collapse; dual packed partial chains
    float ev0 = sBc, ev1 = 0.f;
#pragma unroll
    for (int c = 0; c < 17; c++) {
        const ulonglong2* wcu = (const ulonglong2*)(sW2T + c * 20);  // broadcast
        u64 accA = 0ull, accB = 0ull;
        ulonglong2 w01 = wcu[0];   // rows 0-3
        ulonglong2 w23 = wcu[1];   // rows 4-7
        ulonglong2 w45 = wcu[2];   // rows 8-11
        ulonglong2 w67 = wcu[3];   // rows 12-15
        fma2(accA, xp[0], w01.x);
        fma2(accB, xp[1], w01.y);
        fma2(accA, xp[2], w23.x);
        fma2(accB, xp[3], w23.y);
        fma2(accA, xp[4], w45.x);
        fma2(accB, xp[5], w45.y);
        fma2(accA, xp[6], w67.x);
        fma2(accB, xp[7], w67.y);
        float2 a = unpack2(accA);
        float2 b = unpack2(accB);
        float yc = leaky((a.x + a.y) + (b.x + b.y)
                         + fmaf(x16, sW2T[c * 20 + 16], sB2[c]));
        if (c & 1) ev1 = fmaf(yc, sWc[c], ev1);
        else       ev0 = fmaf(yc, sWc[c], ev0);
    }

    float ex = __expf(ev0 + ev1);
    out[e] = ex;
    atomicAdd(&g_sum[i], ex);
}

// ---------------------------------------------------------------------------
// Kernel 3: out[e] /= sum[i], 4 edges/thread with coalesced int4/float4 and
// batched gathers (MLP=4). Extra blocks re-zero g_deg for the next replay
// (g_deg is not read here, so no ordering hazard).
// ---------------------------------------------------------------------------
__global__ void k_div(const int* __restrict__ ind, float* __restrict__ out,
                      int E, int edgeBlocks, int N) {
    if (blockIdx.x >= edgeBlocks) {
        int n = (blockIdx.x - edgeBlocks) * blockDim.x + threadIdx.x;
        if (n < N) g_deg[n] = 0.f;
        return;
    }
    int base = (blockIdx.x * blockDim.x + threadIdx.x) * 4;
    if (base + 3 < E) {
        int4   i4 = *(const int4*)(ind + base);
        float4 o4 = *(const float4*)(out + base);
        float s0 = g_sum[i4.x], s1 = g_sum[i4.y];
        float s2 = g_sum[i4.z], s3 = g_sum[i4.w];
        o4.x = __fdividef(o4.x, s0);
        o4.y = __fdividef(o4.y, s1);
        o4.z = __fdividef(o4.z, s2);
        o4.w = __fdividef(o4.w, s3);
        *(float4*)(out + base) = o4;
    } else {
        for (int e = base; e < E; e++)
            out[e] = __fdividef(out[e], g_sum[ind[e]]);
    }
}

// ---------------------------------------------------------------------------
extern "C" void kernel_launch(void* const* d_in, const int* in_sizes, int n_in,
                              void* d_out, int out_size) {
    const int*   ind = (const int*)d_in[0];    // [2, E]
    const float* val = (const float*)d_in[1];  // [E]
    const float* f   = (const float*)d_in[2];  // [N, 128]
    const float* W1  = (const float*)d_in[4];  // [256, 16]
    const float* b1  = (const float*)d_in[5];  // [16]
    const float* W2  = (const float*)d_in[6];  // [17, 17]
    const float* b2  = (const float*)d_in[7];  // [17]
    const float* Wc  = (const float*)d_in[8];  // [17, 1]
    const float* bc  = (const float*)d_in[9];  // [1]
    float* out = (float*)d_out;

    int E = in_sizes[1];
    int N = in_sizes[2] / 128;

    int tb = 256;
    int gN = (N + tb - 1) / tb;          // node-count blocks (zeroing)
    int gE = (E + tb - 1) / tb;          // edge-count blocks
    int gE4 = (E + tb * 4 - 1) / (tb * 4);  // 4 edges per thread
    int nodeBlocks = (N + 127) / 128;    // 128-node register-tiled blocks

    k_nodedeg<<<nodeBlocks + gE + gN, tb>>>(f, W1, ind, val, N, E, nodeBlocks, gE);
    k_edge<<<gE, tb>>>(ind, val, b1, W2, b2, Wc, bc, out, E);
    k_div<<<gE4 + gN, tb>>>(ind, out, E, gE4, N);
}